// round 1
// baseline (speedup 1.0000x reference)
#include <cuda_runtime.h>

// ---------------------------------------------------------------------------
// MLS-MPM single step, 500k particles, 64^3 grid.
// Pipeline: zero grid -> P2G scatter (red.global.add.v4.f32) -> grid update
//           -> G2P gather + advection + F update.
// Grid scratch is a __device__ global (4 MB, L2-resident).
// ---------------------------------------------------------------------------

#ifndef NGRID
#define NGRID 64
#endif

namespace {
constexpr int   NG      = NGRID;
constexpr int   GSZ     = NG * NG * NG;        // 262144
constexpr int   NP      = 500000;
constexpr float DXf     = 1.0f / 64.0f;
constexpr float INV_DXf = 64.0f;
constexpr float DTf     = 5e-4f;
// P_VOL = (DX*0.5)^3 = 2^-21 ; P_MASS = 1000 * 2^-21
constexpr float P_MASSf = 4.76837158203125e-4f;
// -DT * P_VOL * 4 * INV_DX^2 = -5e-4 * 2^-21 * 16384 = -3.90625e-6
constexpr float AFF_COEF = -3.90625e-6f;
// 4*INV_DX^2 * DX  (C coefficient with dpos kept in grid units)
constexpr float C_COEF_GRIDU = 256.0f;
}

__device__ float4 g_grid[GSZ];   // (mv.x, mv.y, mv.z, m) then (v.x, v.y, v.z, 0)

// ---------------------------------------------------------------------------
__global__ void __launch_bounds__(256) zero_grid_kernel() {
    int n = blockIdx.x * 256 + threadIdx.x;
    if (n < GSZ) g_grid[n] = make_float4(0.f, 0.f, 0.f, 0.f);
}

// ---------------------------------------------------------------------------
__global__ void __launch_bounds__(256) p2g_kernel(
    const float* __restrict__ x, const float* __restrict__ v,
    const float* __restrict__ C, const float* __restrict__ stress)
{
    int p = blockIdx.x * 256 + threadIdx.x;
    if (p >= NP) return;

    const float px = x[3 * p + 0], py = x[3 * p + 1], pz = x[3 * p + 2];
    const float gx = px * INV_DXf, gy = py * INV_DXf, gz = pz * INV_DXf;
    const int bx = (int)floorf(gx - 0.5f);
    const int by = (int)floorf(gy - 0.5f);
    const int bz = (int)floorf(gz - 0.5f);
    const float fx = gx - (float)bx, fy = gy - (float)by, fz = gz - (float)bz;

    float wx[3], wy[3], wz[3];
    wx[0] = 0.5f * (1.5f - fx) * (1.5f - fx);
    wx[1] = 0.75f - (fx - 1.0f) * (fx - 1.0f);
    wx[2] = 0.5f * (fx - 0.5f) * (fx - 0.5f);
    wy[0] = 0.5f * (1.5f - fy) * (1.5f - fy);
    wy[1] = 0.75f - (fy - 1.0f) * (fy - 1.0f);
    wy[2] = 0.5f * (fy - 0.5f) * (fy - 0.5f);
    wz[0] = 0.5f * (1.5f - fz) * (1.5f - fz);
    wz[1] = 0.75f - (fz - 1.0f) * (fz - 1.0f);
    wz[2] = 0.5f * (fz - 0.5f) * (fz - 0.5f);

    // affine = stress * AFF_COEF + P_MASS * C ; fold DX (dpos = (off-fx)*DX)
    float A[3][3];
#pragma unroll
    for (int i = 0; i < 3; i++)
#pragma unroll
        for (int j = 0; j < 3; j++)
            A[i][j] = (stress[9 * p + 3 * i + j] * AFF_COEF +
                       P_MASSf * C[9 * p + 3 * i + j]) * DXf;

    const float mv0 = P_MASSf * v[3 * p + 0];
    const float mv1 = P_MASSf * v[3 * p + 1];
    const float mv2 = P_MASSf * v[3 * p + 2];

#pragma unroll
    for (int i = 0; i < 3; i++) {
        const float dpi = (float)i - fx;
#pragma unroll
        for (int j = 0; j < 3; j++) {
            const float dpj = (float)j - fy;
            const float wij = wx[i] * wy[j];
            const int rowbase = ((bx + i) * NG + (by + j)) * NG + bz;
#pragma unroll
            for (int k = 0; k < 3; k++) {
                const float dpk = (float)k - fz;
                const float w = wij * wz[k];
                const float m0 = mv0 + A[0][0] * dpi + A[0][1] * dpj + A[0][2] * dpk;
                const float m1 = mv1 + A[1][0] * dpi + A[1][1] * dpj + A[1][2] * dpk;
                const float m2 = mv2 + A[2][0] * dpi + A[2][1] * dpj + A[2][2] * dpk;
                float4* gp = &g_grid[rowbase + k];
                asm volatile(
                    "red.global.add.v4.f32 [%0], {%1, %2, %3, %4};"
                    :: "l"(gp), "f"(w * m0), "f"(w * m1), "f"(w * m2),
                       "f"(w * P_MASSf)
                    : "memory");
            }
        }
    }
}

// ---------------------------------------------------------------------------
__global__ void __launch_bounds__(256) grid_kernel() {
    int n = blockIdx.x * 256 + threadIdx.x;
    if (n >= GSZ) return;
    float4 g = g_grid[n];
    float vx = 0.f, vy = 0.f, vz = 0.f;
    if (g.w > 0.0f) {
        const float inv = 1.0f / fmaxf(g.w, 1e-10f);
        vx = g.x * inv;
        vy = g.y * inv + DTf * (-9.8f);
        vz = g.z * inv;
    }
    const int i = n >> 12;
    const int j = (n >> 6) & 63;
    const int k = n & 63;
    if ((i < 3 && vx < 0.f) || (i >= NG - 3 && vx > 0.f)) vx = 0.f;
    if ((j < 3 && vy < 0.f) || (j >= NG - 3 && vy > 0.f)) vy = 0.f;
    if ((k < 3 && vz < 0.f) || (k >= NG - 3 && vz > 0.f)) vz = 0.f;
    g_grid[n] = make_float4(vx, vy, vz, 0.f);
}

// ---------------------------------------------------------------------------
__global__ void __launch_bounds__(256) g2p_kernel(
    const float* __restrict__ x, const float* __restrict__ F,
    float* __restrict__ out)
{
    int p = blockIdx.x * 256 + threadIdx.x;
    if (p >= NP) return;

    const float px = x[3 * p + 0], py = x[3 * p + 1], pz = x[3 * p + 2];
    const float gx = px * INV_DXf, gy = py * INV_DXf, gz = pz * INV_DXf;
    const int bx = (int)floorf(gx - 0.5f);
    const int by = (int)floorf(gy - 0.5f);
    const int bz = (int)floorf(gz - 0.5f);
    const float fx = gx - (float)bx, fy = gy - (float)by, fz = gz - (float)bz;

    float wx[3], wy[3], wz[3];
    wx[0] = 0.5f * (1.5f - fx) * (1.5f - fx);
    wx[1] = 0.75f - (fx - 1.0f) * (fx - 1.0f);
    wx[2] = 0.5f * (fx - 0.5f) * (fx - 0.5f);
    wy[0] = 0.5f * (1.5f - fy) * (1.5f - fy);
    wy[1] = 0.75f - (fy - 1.0f) * (fy - 1.0f);
    wy[2] = 0.5f * (fy - 0.5f) * (fy - 0.5f);
    wz[0] = 0.5f * (1.5f - fz) * (1.5f - fz);
    wz[1] = 0.75f - (fz - 1.0f) * (fz - 1.0f);
    wz[2] = 0.5f * (fz - 0.5f) * (fz - 0.5f);

    float vn0 = 0.f, vn1 = 0.f, vn2 = 0.f;
    float B[3][3] = {{0.f, 0.f, 0.f}, {0.f, 0.f, 0.f}, {0.f, 0.f, 0.f}};

#pragma unroll
    for (int i = 0; i < 3; i++) {
        const float dpi = (float)i - fx;
#pragma unroll
        for (int j = 0; j < 3; j++) {
            const float dpj = (float)j - fy;
            const float wij = wx[i] * wy[j];
            const int rowbase = ((bx + i) * NG + (by + j)) * NG + bz;
#pragma unroll
            for (int k = 0; k < 3; k++) {
                const float dpk = (float)k - fz;
                const float w = wij * wz[k];
                const float4 g = __ldg(&g_grid[rowbase + k]);
                vn0 += w * g.x; vn1 += w * g.y; vn2 += w * g.z;
                B[0][0] += w * g.x * dpi; B[0][1] += w * g.x * dpj; B[0][2] += w * g.x * dpk;
                B[1][0] += w * g.y * dpi; B[1][1] += w * g.y * dpj; B[1][2] += w * g.y * dpk;
                B[2][0] += w * g.z * dpi; B[2][1] += w * g.z * dpj; B[2][2] += w * g.z * dpk;
            }
        }
    }

    float Cn[3][3];
#pragma unroll
    for (int i = 0; i < 3; i++)
#pragma unroll
        for (int j = 0; j < 3; j++)
            Cn[i][j] = C_COEF_GRIDU * B[i][j];

    // x_next
    out[3 * p + 0] = px + DTf * vn0;
    out[3 * p + 1] = py + DTf * vn1;
    out[3 * p + 2] = pz + DTf * vn2;
    // v_next
    float* ov = out + (size_t)3 * NP;
    ov[3 * p + 0] = vn0; ov[3 * p + 1] = vn1; ov[3 * p + 2] = vn2;
    // C_next
    float* oc = out + (size_t)6 * NP;
#pragma unroll
    for (int i = 0; i < 3; i++)
#pragma unroll
        for (int j = 0; j < 3; j++)
            oc[9 * p + 3 * i + j] = Cn[i][j];
    // F_next = (I + DT*C_next) @ F
    float Fin[3][3];
#pragma unroll
    for (int i = 0; i < 3; i++)
#pragma unroll
        for (int j = 0; j < 3; j++)
            Fin[i][j] = F[9 * p + 3 * i + j];
    float* of = out + (size_t)15 * NP;
#pragma unroll
    for (int i = 0; i < 3; i++) {
        const float m0 = (i == 0 ? 1.f : 0.f) + DTf * Cn[i][0];
        const float m1 = (i == 1 ? 1.f : 0.f) + DTf * Cn[i][1];
        const float m2 = (i == 2 ? 1.f : 0.f) + DTf * Cn[i][2];
#pragma unroll
        for (int j = 0; j < 3; j++)
            of[9 * p + 3 * i + j] = m0 * Fin[0][j] + m1 * Fin[1][j] + m2 * Fin[2][j];
    }
}

// ---------------------------------------------------------------------------
extern "C" void kernel_launch(void* const* d_in, const int* in_sizes, int n_in,
                              void* d_out, int out_size)
{
    const float* x      = (const float*)d_in[0];
    const float* v      = (const float*)d_in[1];
    const float* C      = (const float*)d_in[2];
    const float* F      = (const float*)d_in[3];
    const float* stress = (const float*)d_in[4];
    float* out = (float*)d_out;

    const int gblocks = (GSZ + 255) / 256;
    const int pblocks = (NP + 255) / 256;

    zero_grid_kernel<<<gblocks, 256>>>();
    p2g_kernel<<<pblocks, 256>>>(x, v, C, stress);
    grid_kernel<<<gblocks, 256>>>();
    g2p_kernel<<<pblocks, 256>>>(x, F, out);
}